// round 7
// baseline (speedup 1.0000x reference)
#include <cuda_runtime.h>

// Volume rendering (NeRF-style) on GB300 — R7: persistent warps with a
// software-pipelined double buffer. R6 showed per-warp MLP depth is not the
// limiter (occ 63% vs 82% -> same 89% DRAM). Hypothesis: short-lived CTAs
// create load-free windows (scan+reduce+exit+CLC replacement) that cap DRAM
// duty cycle at ~89%. Persistent warps grid-stride over rays and issue ray
// i+1's 5 LDG.128s before computing ray i, keeping loads continuously
// outstanding. Streaming (.cs) hints retained (R4: 98.1 -> 96.3 us).
//
// Inputs (metadata order): rgb [N,128,3] f32, density [N,128,1] f32,
//                          distances [N,128] f32. Output: [N,3] f32.

#ifndef FULL_MASK
#define FULL_MASK 0xffffffffu
#endif

static constexpr int N_SAMPLES = 128;
static constexpr float FAR_DELTA = 1e10f;
static constexpr int WARPS_PER_BLOCK = 8;
static constexpr int BLOCKS_PER_SM = 4;
static constexpr int NUM_SMS = 148;   // GB300: 148+ SMs; grid-stride handles any count

struct RayData {
    float4 d, s, c0, c1, c2;
};

__device__ __forceinline__ void load_ray(const float* __restrict__ rgb,
                                         const float* __restrict__ density,
                                         const float* __restrict__ dist,
                                         long ray, int lane, RayData& r)
{
    const long base = ray * N_SAMPLES;
    r.d = __ldcs(reinterpret_cast<const float4*>(dist    + base) + lane);
    r.s = __ldcs(reinterpret_cast<const float4*>(density + base) + lane);
    const float4* rgb4 = reinterpret_cast<const float4*>(rgb + base * 3) + lane * 3;
    r.c0 = __ldcs(rgb4 + 0);
    r.c1 = __ldcs(rgb4 + 1);
    r.c2 = __ldcs(rgb4 + 2);
}

__device__ __forceinline__ void render_ray(const RayData& r, int lane,
                                           float* __restrict__ out, long ray)
{
    // ---- deltas ----
    const float d_next = __shfl_down_sync(FULL_MASK, r.d.x, 1);
    const float dl0 = r.d.y - r.d.x;
    const float dl1 = r.d.z - r.d.y;
    const float dl2 = r.d.w - r.d.z;
    const float dl3 = (lane == 31) ? FAR_DELTA : (d_next - r.d.w);

    // ---- omega = exp(-sigma * delta) ----
    const float w0 = __expf(-r.s.x * dl0);
    const float w1 = __expf(-r.s.y * dl1);
    const float w2 = __expf(-r.s.z * dl2);
    const float w3 = __expf(-r.s.w * dl3);

    // ---- exclusive cumprod across the warp ----
    float incl = w0 * w1 * w2 * w3;
    #pragma unroll
    for (int off = 1; off < 32; off <<= 1) {
        const float v = __shfl_up_sync(FULL_MASK, incl, off);
        if (lane >= off) incl *= v;
    }
    float T = __shfl_up_sync(FULL_MASK, incl, 1);
    if (lane == 0) T = 1.0f;

    // ---- local weights ----
    const float t0 = T;
    const float t1 = t0 * w0;
    const float t2 = t1 * w1;
    const float t3 = t2 * w2;
    const float wt0 = t0 - t1;
    const float wt1 = t1 - t2;
    const float wt2 = t2 - t3;
    const float wt3 = t3 * (1.0f - w3);

    // rgb layout per lane: s0=(c0.x,c0.y,c0.z) s1=(c0.w,c1.x,c1.y)
    //                      s2=(c1.z,c1.w,c2.x) s3=(c2.y,c2.z,c2.w)
    float accR = wt0 * r.c0.x + wt1 * r.c0.w + wt2 * r.c1.z + wt3 * r.c2.y;
    float accG = wt0 * r.c0.y + wt1 * r.c1.x + wt2 * r.c1.w + wt3 * r.c2.z;
    float accB = wt0 * r.c0.z + wt1 * r.c1.y + wt2 * r.c2.x + wt3 * r.c2.w;

    #pragma unroll
    for (int off = 16; off > 0; off >>= 1) {
        accR += __shfl_xor_sync(FULL_MASK, accR, off);
        accG += __shfl_xor_sync(FULL_MASK, accG, off);
        accB += __shfl_xor_sync(FULL_MASK, accB, off);
    }

    if (lane == 0) {
        float* o = out + ray * 3;
        o[0] = accR;
        o[1] = accG;
        o[2] = accB;
    }
}

__global__ void __launch_bounds__(WARPS_PER_BLOCK * 32, BLOCKS_PER_SM)
volrend_kernel(const float* __restrict__ rgb,
               const float* __restrict__ density,
               const float* __restrict__ dist,
               float* __restrict__ out,
               int n_rays)
{
    const int warp_gid = (blockIdx.x * blockDim.x + threadIdx.x) >> 5;
    const int lane     = threadIdx.x & 31;
    const int stride   = (gridDim.x * blockDim.x) >> 5;   // total warps

    long ray = warp_gid;
    if (ray >= n_rays) return;

    RayData cur;
    load_ray(rgb, density, dist, ray, lane, cur);

    while (true) {
        const long next = ray + stride;
        const bool has_next = (next < n_rays);

        RayData nxt;
        if (has_next)
            load_ray(rgb, density, dist, next, lane, nxt);  // overlaps with scan below

        render_ray(cur, lane, out, ray);

        if (!has_next) break;
        cur = nxt;
        ray = next;
    }
}

extern "C" void kernel_launch(void* const* d_in, const int* in_sizes, int n_in,
                              void* d_out, int out_size)
{
    const float* rgb     = (const float*)d_in[0];
    const float* density = (const float*)d_in[1];
    const float* dist    = (const float*)d_in[2];
    float* out = (float*)d_out;

    const int n_rays = in_sizes[2] / N_SAMPLES;   // distances: [N, 128]

    const int threads = WARPS_PER_BLOCK * 32;
    int blocks = NUM_SMS * BLOCKS_PER_SM;         // persistent: 4 CTAs per SM
    const int max_blocks = (n_rays + WARPS_PER_BLOCK - 1) / WARPS_PER_BLOCK;
    if (blocks > max_blocks) blocks = max_blocks;

    volrend_kernel<<<blocks, threads>>>(rgb, density, dist, out, n_rays);
}

// round 10
// speedup vs baseline: 1.0376x; 1.0376x over previous
#include <cuda_runtime.h>

// Volume rendering (NeRF-style) on GB300 — R8 re-resubmit (2x infra timeout):
// 2 rays/warp (best DRAM% so far, 89.0) + explicit min-blocks hint to
// recover occupancy. R7 falsified the persistent-CTA theory (occ collapse
// -> 85.1% DRAM); R6 showed 10 front-batched LDG.128s/warp edges out 5 even
// at lower occupancy. __launch_bounds__(256, 7): 34 regs x 256 thr x 7 CTAs
// fits the 64K register file -> 56 warps/SM without spills.
//
// Inputs (metadata order): rgb [N,128,3] f32, density [N,128,1] f32,
//                          distances [N,128] f32. Output: [N,3] f32.
//
// Per ray:
//   delta_i  = t_{i+1} - t_i   (last sample: 1e10)
//   omega_i  = exp(-density_i * delta_i)      (= 1 - alpha_i)
//   T_i      = exclusive cumprod(omega)       (warp shfl scan)
//   weight_i = (1 - omega_i) * T_i
//   out      = sum_i weight_i * rgb_i

#ifndef FULL_MASK
#define FULL_MASK 0xffffffffu
#endif

static constexpr int N_SAMPLES = 128;
static constexpr float FAR_DELTA = 1e10f;
static constexpr int RAYS_PER_WARP = 2;
static constexpr int WARPS_PER_BLOCK = 8;

__global__ void __launch_bounds__(WARPS_PER_BLOCK * 32, 7)
volrend_kernel(const float* __restrict__ rgb,
               const float* __restrict__ density,
               const float* __restrict__ dist,
               float* __restrict__ out,
               int n_rays)
{
    const int warp_idx = (blockIdx.x * blockDim.x + threadIdx.x) >> 5;
    const int lane     = threadIdx.x & 31;
    const int rayA = warp_idx * RAYS_PER_WARP;
    const int rayB = rayA + 1;
    if (rayA >= n_rays) return;

    const long baseA = (long)rayA * N_SAMPLES;
    const long baseB = (long)rayB * N_SAMPLES;

    // ---- front-batched streaming loads: 10 x LDG.128 ----
    const float4 dA = __ldcs(reinterpret_cast<const float4*>(dist    + baseA) + lane);
    const float4 dB = __ldcs(reinterpret_cast<const float4*>(dist    + baseB) + lane);
    const float4 sA = __ldcs(reinterpret_cast<const float4*>(density + baseA) + lane);
    const float4 sB = __ldcs(reinterpret_cast<const float4*>(density + baseB) + lane);
    const float4* rgbA = reinterpret_cast<const float4*>(rgb + baseA * 3) + lane * 3;
    const float4* rgbB = reinterpret_cast<const float4*>(rgb + baseB * 3) + lane * 3;
    const float4 a0 = __ldcs(rgbA + 0);
    const float4 a1 = __ldcs(rgbA + 1);
    const float4 a2 = __ldcs(rgbA + 2);
    const float4 b0 = __ldcs(rgbB + 0);
    const float4 b1 = __ldcs(rgbB + 1);
    const float4 b2 = __ldcs(rgbB + 2);

    // ---- deltas ----
    const float dA_next = __shfl_down_sync(FULL_MASK, dA.x, 1);
    const float dB_next = __shfl_down_sync(FULL_MASK, dB.x, 1);
    const float aL0 = dA.y - dA.x, aL1 = dA.z - dA.y, aL2 = dA.w - dA.z;
    const float aL3 = (lane == 31) ? FAR_DELTA : (dA_next - dA.w);
    const float bL0 = dB.y - dB.x, bL1 = dB.z - dB.y, bL2 = dB.w - dB.z;
    const float bL3 = (lane == 31) ? FAR_DELTA : (dB_next - dB.w);

    // ---- omega = exp(-sigma * delta) ----
    const float aw0 = __expf(-sA.x * aL0);
    const float aw1 = __expf(-sA.y * aL1);
    const float aw2 = __expf(-sA.z * aL2);
    const float aw3 = __expf(-sA.w * aL3);
    const float bw0 = __expf(-sB.x * bL0);
    const float bw1 = __expf(-sB.y * bL1);
    const float bw2 = __expf(-sB.z * bL2);
    const float bw3 = __expf(-sB.w * bL3);

    // ---- two independent exclusive-cumprod scans (interleaved by ILP) ----
    float inclA = aw0 * aw1 * aw2 * aw3;
    float inclB = bw0 * bw1 * bw2 * bw3;
    #pragma unroll
    for (int off = 1; off < 32; off <<= 1) {
        const float vA = __shfl_up_sync(FULL_MASK, inclA, off);
        const float vB = __shfl_up_sync(FULL_MASK, inclB, off);
        if (lane >= off) { inclA *= vA; inclB *= vB; }
    }
    float TA = __shfl_up_sync(FULL_MASK, inclA, 1);
    float TB = __shfl_up_sync(FULL_MASK, inclB, 1);
    if (lane == 0) { TA = 1.0f; TB = 1.0f; }

    // ---- local weights ----
    const float at0 = TA, at1 = at0 * aw0, at2 = at1 * aw1, at3 = at2 * aw2;
    const float awt0 = at0 - at1, awt1 = at1 - at2, awt2 = at2 - at3;
    const float awt3 = at3 * (1.0f - aw3);
    const float bt0 = TB, bt1 = bt0 * bw0, bt2 = bt1 * bw1, bt3 = bt2 * bw2;
    const float bwt0 = bt0 - bt1, bwt1 = bt1 - bt2, bwt2 = bt2 - bt3;
    const float bwt3 = bt3 * (1.0f - bw3);

    // rgb layout per lane: s0=(c0.x,c0.y,c0.z) s1=(c0.w,c1.x,c1.y)
    //                      s2=(c1.z,c1.w,c2.x) s3=(c2.y,c2.z,c2.w)
    float arR = awt0 * a0.x + awt1 * a0.w + awt2 * a1.z + awt3 * a2.y;
    float arG = awt0 * a0.y + awt1 * a1.x + awt2 * a1.w + awt3 * a2.z;
    float arB = awt0 * a0.z + awt1 * a1.y + awt2 * a2.x + awt3 * a2.w;
    float brR = bwt0 * b0.x + bwt1 * b0.w + bwt2 * b1.z + bwt3 * b2.y;
    float brG = bwt0 * b0.y + bwt1 * b1.x + bwt2 * b1.w + bwt3 * b2.z;
    float brB = bwt0 * b0.z + bwt1 * b1.y + bwt2 * b2.x + bwt3 * b2.w;

    // ---- warp reductions (both rays interleaved) ----
    #pragma unroll
    for (int off = 16; off > 0; off >>= 1) {
        arR += __shfl_xor_sync(FULL_MASK, arR, off);
        brR += __shfl_xor_sync(FULL_MASK, brR, off);
        arG += __shfl_xor_sync(FULL_MASK, arG, off);
        brG += __shfl_xor_sync(FULL_MASK, brG, off);
        arB += __shfl_xor_sync(FULL_MASK, arB, off);
        brB += __shfl_xor_sync(FULL_MASK, brB, off);
    }

    if (lane == 0) {
        float* o = out + (long)rayA * 3;
        o[0] = arR; o[1] = arG; o[2] = arB;
        o[3] = brR; o[4] = brG; o[5] = brB;
    }
}

extern "C" void kernel_launch(void* const* d_in, const int* in_sizes, int n_in,
                              void* d_out, int out_size)
{
    const float* rgb     = (const float*)d_in[0];
    const float* density = (const float*)d_in[1];
    const float* dist    = (const float*)d_in[2];
    float* out = (float*)d_out;

    const int n_rays = in_sizes[2] / N_SAMPLES;   // distances: [N, 128]

    const int threads = WARPS_PER_BLOCK * 32;
    const int rays_per_block = WARPS_PER_BLOCK * RAYS_PER_WARP;
    const int blocks = (n_rays + rays_per_block - 1) / rays_per_block;

    volrend_kernel<<<blocks, threads>>>(rgb, density, dist, out, n_rays);
}

// round 11
// speedup vs baseline: 1.0484x; 1.0105x over previous
#include <cuda_runtime.h>

// Volume rendering (NeRF-style) on GB300 — FINAL (= R5 config, best measured).
//
// Session evidence (DRAM% / wall us):
//   R1 strided rgb           87.8 / 98.1
//   R2 unit-stride rgb+smem  87.5 / 98.5   (access pattern irrelevant)
//   R5 R1 + __ldcs hints     88.8 / 96.3   <- WIN, this kernel
//   R6 2 rays/warp           89.0 / 97.0   (MLP depth: no wall gain)
//   R7 persistent dbl-buf    85.1 / 102.5  (occ collapse: falsified)
//   R8 2 rays + min-blocks 7 86.2 / 98.8   (reg squeeze de-batches loads)
// ~89% DRAM busy (~7.05 TB/s) is the ceiling for this 674 MB read-once
// stream; all structural levers tested and falsified.
//
// Inputs (metadata order): rgb [N,128,3] f32, density [N,128,1] f32,
//                          distances [N,128] f32. Output: [N,3] f32.
//
// One warp per ray; 4 consecutive samples per lane.
//   delta_i  = t_{i+1} - t_i   (last sample: 1e10)
//   omega_i  = exp(-density_i * delta_i)      (= 1 - alpha_i)
//   T_i      = exclusive cumprod(omega)       (warp shfl scan)
//   weight_i = (1 - omega_i) * T_i
//   out      = sum_i weight_i * rgb_i

#ifndef FULL_MASK
#define FULL_MASK 0xffffffffu
#endif

static constexpr int N_SAMPLES = 128;
static constexpr float FAR_DELTA = 1e10f;

__global__ void __launch_bounds__(256, 8)
volrend_kernel(const float* __restrict__ rgb,
               const float* __restrict__ density,
               const float* __restrict__ dist,
               float* __restrict__ out,
               int n_rays)
{
    const int warp_id = (blockIdx.x * blockDim.x + threadIdx.x) >> 5;
    const int lane    = threadIdx.x & 31;
    if (warp_id >= n_rays) return;

    const long base = (long)warp_id * N_SAMPLES;

    // ---- coalesced streaming loads: 4 samples per lane ----
    const float4 d4 = __ldcs(reinterpret_cast<const float4*>(dist    + base) + lane);
    const float4 s4 = __ldcs(reinterpret_cast<const float4*>(density + base) + lane);
    const float4* rgb4 = reinterpret_cast<const float4*>(rgb + base * 3) + lane * 3;
    const float4 c0 = __ldcs(rgb4 + 0);
    const float4 c1 = __ldcs(rgb4 + 1);
    const float4 c2 = __ldcs(rgb4 + 2);

    // ---- deltas (next lane's first distance via shfl) ----
    const float d_next = __shfl_down_sync(FULL_MASK, d4.x, 1);
    const float dl0 = d4.y - d4.x;
    const float dl1 = d4.z - d4.y;
    const float dl2 = d4.w - d4.z;
    const float dl3 = (lane == 31) ? FAR_DELTA : (d_next - d4.w);

    // ---- omega = exp(-sigma * delta) = 1 - alpha ----
    const float w0 = __expf(-s4.x * dl0);
    const float w1 = __expf(-s4.y * dl1);
    const float w2 = __expf(-s4.z * dl2);
    const float w3 = __expf(-s4.w * dl3);

    // ---- exclusive cumprod across the warp ----
    const float p = w0 * w1 * w2 * w3;     // this lane's full product
    float incl = p;                        // inclusive scan of lane products
    #pragma unroll
    for (int off = 1; off < 32; off <<= 1) {
        const float v = __shfl_up_sync(FULL_MASK, incl, off);
        if (lane >= off) incl *= v;
    }
    float T = __shfl_up_sync(FULL_MASK, incl, 1);   // exclusive: prev lane's inclusive
    if (lane == 0) T = 1.0f;

    // ---- local weights: T walks through this lane's 4 samples ----
    const float t0 = T;
    const float t1 = t0 * w0;
    const float t2 = t1 * w1;
    const float t3 = t2 * w2;
    const float wt0 = t0 - t1;             // = alpha0 * T0
    const float wt1 = t1 - t2;
    const float wt2 = t2 - t3;
    const float wt3 = t3 * (1.0f - w3);

    // rgb layout per lane: s0=(c0.x,c0.y,c0.z) s1=(c0.w,c1.x,c1.y)
    //                      s2=(c1.z,c1.w,c2.x) s3=(c2.y,c2.z,c2.w)
    float accR = wt0 * c0.x + wt1 * c0.w + wt2 * c1.z + wt3 * c2.y;
    float accG = wt0 * c0.y + wt1 * c1.x + wt2 * c1.w + wt3 * c2.z;
    float accB = wt0 * c0.z + wt1 * c1.y + wt2 * c2.x + wt3 * c2.w;

    // ---- warp reduction over the 4-sample partial sums ----
    #pragma unroll
    for (int off = 16; off > 0; off >>= 1) {
        accR += __shfl_xor_sync(FULL_MASK, accR, off);
        accG += __shfl_xor_sync(FULL_MASK, accG, off);
        accB += __shfl_xor_sync(FULL_MASK, accB, off);
    }

    if (lane == 0) {
        float* o = out + (long)warp_id * 3;
        o[0] = accR;
        o[1] = accG;
        o[2] = accB;
    }
}

extern "C" void kernel_launch(void* const* d_in, const int* in_sizes, int n_in,
                              void* d_out, int out_size)
{
    const float* rgb     = (const float*)d_in[0];
    const float* density = (const float*)d_in[1];
    const float* dist    = (const float*)d_in[2];
    float* out = (float*)d_out;

    const int n_rays = in_sizes[2] / N_SAMPLES;   // distances: [N, 128]

    const int threads = 256;                       // 8 warps = 8 rays / block
    const int rays_per_block = threads / 32;
    const int blocks = (n_rays + rays_per_block - 1) / rays_per_block;

    volrend_kernel<<<blocks, threads>>>(rgb, density, dist, out, n_rays);
}